// round 9
// baseline (speedup 1.0000x reference)
#include <cuda_runtime.h>
#include <cuda_fp16.h>
#include <math.h>

#define NN 50000
#define EE 800000
#define RR 8
#define BB 4
#define NB ((NN + 255) / 256)

// ---------------- scratch (device globals; no allocation) ----------------
__device__ float  g_x1[NN * 64];
__device__ float  g_x2[NN * 128];
__device__ float  g_x3[NN * 32];
__device__ __half g_h[NN * 128];        // GAT features, fp16
__device__ float  g_al[NN * 8];
__device__ float  g_z[(size_t)NN * 512];
__device__ int    g_cnt[NN * RR];
__device__ int    g_row_off[NN + 1];
__device__ int    g_cursor[NN];
__device__ int    g_adj[EE];            // src | (etype<<16)
__device__ int    g_pos[EE];
__device__ float  g_ev[(size_t)EE * 4];
__device__ int    g_nodescan[NN];
__device__ int    g_blocksum[NB];
__device__ int    g_blockoff[NB];

__device__ __forceinline__ float4 ld4(const float* p) { return __ldg((const float4*)p); }
__device__ __forceinline__ float2 ld2(const float* p) { return __ldg((const float2*)p); }

template <int VW>
__device__ __forceinline__ void ldv(float (&d)[VW], const float* p) {
    if (VW == 2) {
        float2 v = ld2(p);
        d[0] = v.x; d[1] = v.y;
    } else {
        float4 v = ld4(p);
        d[0] = v.x; d[1] = v.y; d[2] = v.z; d[3] = v.w;
    }
}

// load 4 halves -> float4
__device__ __forceinline__ float4 ldh4(const __half* p) {
    uint2 raw = __ldg((const uint2*)p);
    __half2 a = *(__half2*)&raw.x;
    __half2 b = *(__half2*)&raw.y;
    float2 fa = __half22float2(a), fb = __half22float2(b);
    return make_float4(fa.x, fa.y, fb.x, fb.y);
}
// load 2 halves -> float2
__device__ __forceinline__ float2 ldh2(const __half* p) {
    __half2 h = __ldg((const __half2*)p);
    return __half22float2(h);
}

// ---------------- CSR build ----------------
__global__ void zero_int(int* __restrict__ p, int n) {
    int i = blockIdx.x * blockDim.x + threadIdx.x;
    if (i < n) p[i] = 0;
}

__global__ void hist_kernel(const int* __restrict__ dst, const int* __restrict__ et) {
    int e = blockIdx.x * blockDim.x + threadIdx.x;
    if (e < EE) atomicAdd(&g_cnt[dst[e] * RR + et[e]], 1);
}

__global__ void scanA() {
    __shared__ int sh[256];
    int t = threadIdx.x;
    int n = blockIdx.x * 256 + t;
    int deg = 0;
    if (n < NN) {
#pragma unroll
        for (int r = 0; r < RR; r++) deg += g_cnt[n * RR + r];
    }
    int val = deg;
    sh[t] = val;
    __syncthreads();
    for (int d = 1; d < 256; d <<= 1) {
        int a = (t >= d) ? sh[t - d] : 0;
        __syncthreads();
        val += a;
        sh[t] = val;
        __syncthreads();
    }
    if (n < NN) g_nodescan[n] = val - deg;
    if (t == 255) g_blocksum[blockIdx.x] = val;
}

__global__ void scanB() {
    __shared__ int sh[256];
    int t = threadIdx.x;
    int own = (t < NB) ? g_blocksum[t] : 0;
    int val = own;
    sh[t] = val;
    __syncthreads();
    for (int d = 1; d < 256; d <<= 1) {
        int a = (t >= d) ? sh[t - d] : 0;
        __syncthreads();
        val += a;
        sh[t] = val;
        __syncthreads();
    }
    if (t < NB) g_blockoff[t] = val - own;
    if (t == NB - 1) g_row_off[NN] = val;
}

__global__ void scanC() {
    int n = blockIdx.x * 256 + threadIdx.x;
    if (n < NN) {
        int off = g_blockoff[blockIdx.x] + g_nodescan[n];
        g_row_off[n] = off;
        g_cursor[n] = off;
    }
}

__global__ void fill_kernel(const int* __restrict__ src, const int* __restrict__ dst,
                            const int* __restrict__ et) {
    int e = blockIdx.x * blockDim.x + threadIdx.x;
    if (e < EE) {
        int d = dst[e];
        int pos = atomicAdd(&g_cursor[d], 1);
        g_adj[pos] = src[e] | (et[e] << 16);
        g_pos[e] = pos;
    }
}

// ---------------- RGCN: warp-per-node gather -> z[n, BB*IN] ----------------
template <int IN, int WPB>
__global__ __launch_bounds__(32 * WPB) void rgcn_gather_z(
    const float* __restrict__ x, const float* __restrict__ comp) {
    const int VW = IN / 32;
    __shared__ float wsh[WPB][RR * BB];
    int wid = threadIdx.x >> 5, lane = threadIdx.x & 31;
    int n = blockIdx.x * WPB + wid;
    if (n >= NN) return;

    if (lane < RR) {
        float ic = 1.f / fmaxf((float)g_cnt[n * RR + lane], 1.f);
#pragma unroll
        for (int b = 0; b < BB; b++) wsh[wid][lane * BB + b] = comp[lane * BB + b] * ic;
    }
    __syncwarp();

    float acc[BB][VW];
#pragma unroll
    for (int b = 0; b < BB; b++)
#pragma unroll
        for (int c = 0; c < VW; c++) acc[b][c] = 0.f;

    int k1 = g_row_off[n + 1];
    int k = g_row_off[n];
    for (; k + 4 <= k1; k += 4) {
        int v[4];
        float xr[4][VW];
#pragma unroll
        for (int j = 0; j < 4; j++) {
            v[j] = g_adj[k + j];
            ldv<VW>(xr[j], x + (size_t)(v[j] & 0xFFFF) * IN + VW * lane);
        }
#pragma unroll
        for (int j = 0; j < 4; j++) {
            const float* w = &wsh[wid][(v[j] >> 16) * BB];
#pragma unroll
            for (int b = 0; b < BB; b++)
#pragma unroll
                for (int c = 0; c < VW; c++) acc[b][c] += w[b] * xr[j][c];
        }
    }
    for (; k < k1; k++) {
        int v = g_adj[k];
        float xr[VW];
        ldv<VW>(xr, x + (size_t)(v & 0xFFFF) * IN + VW * lane);
        const float* w = &wsh[wid][(v >> 16) * BB];
#pragma unroll
        for (int b = 0; b < BB; b++)
#pragma unroll
            for (int c = 0; c < VW; c++) acc[b][c] += w[b] * xr[c];
    }
    float* zp = g_z + (size_t)n * (BB * IN);
#pragma unroll
    for (int b = 0; b < BB; b++) {
        if (VW == 2) {
            float2 o; o.x = acc[b][0]; o.y = acc[b][1];
            *(float2*)(zp + b * IN + 2 * lane) = o;
        } else {
            float4 o; o.x = acc[b][0]; o.y = acc[b][1]; o.z = acc[b][VW - 2]; o.w = acc[b][VW - 1];
            *(float4*)(zp + b * IN + 4 * lane) = o;
        }
    }
}

// ---------------- tiled GEMM: C = A1@W1 + A2@W2 + bias, relu ----------------
template <int K1, int K2, int N, int MT>
__global__ __launch_bounds__(128) void gemm_rgcn(
    const float* __restrict__ A1, const float* __restrict__ A2,
    const float* __restrict__ W1, const float* __restrict__ W2,
    const float* __restrict__ bias, float* __restrict__ C) {
    const int KT = 32;
    const int TX = N / 4, TY = 128 / TX, MR = MT / TY;
    __shared__ float At[MT][KT + 4];
    __shared__ float Wt[KT][N];
    int tid = threadIdx.x;
    int tx = tid % TX, ty = tid / TX;
    int m0 = blockIdx.x * MT;
    float acc[MR][4];
#pragma unroll
    for (int r = 0; r < MR; r++)
        for (int j = 0; j < 4; j++) acc[r][j] = 0.f;

    const int T1 = K1 / KT, T2 = K2 / KT;
    for (int t = 0; t < T1 + T2; t++) {
        const float* A; const float* Wsrc;
        int ks, kstride;
        if (t < T1) { A = A1; ks = t * KT; kstride = K1; Wsrc = W1 + t * KT * N; }
        else        { A = A2; ks = (t - T1) * KT; kstride = K2; Wsrc = W2 + (t - T1) * KT * N; }
        __syncthreads();
        const int FR = KT / 4;
        for (int idx = tid; idx < MT * FR; idx += 128) {
            int m = idx / FR, kq = idx % FR;
            int gm = m0 + m; if (gm >= NN) gm = NN - 1;
            *(float4*)&At[m][4 * kq] = ld4(A + (size_t)gm * kstride + ks + 4 * kq);
        }
        for (int idx = tid; idx < KT * N / 4; idx += 128) {
            int row = idx / (N / 4), cq = idx % (N / 4);
            *(float4*)&Wt[row][4 * cq] = ld4(Wsrc + row * N + 4 * cq);
        }
        __syncthreads();
#pragma unroll
        for (int kk = 0; kk < KT; kk += 4) {
            float4 wv0 = *(const float4*)&Wt[kk + 0][tx * 4];
            float4 wv1 = *(const float4*)&Wt[kk + 1][tx * 4];
            float4 wv2 = *(const float4*)&Wt[kk + 2][tx * 4];
            float4 wv3 = *(const float4*)&Wt[kk + 3][tx * 4];
#pragma unroll
            for (int r = 0; r < MR; r++) {
                float4 av = *(const float4*)&At[r * TY + ty][kk];
                acc[r][0] += av.x * wv0.x + av.y * wv1.x + av.z * wv2.x + av.w * wv3.x;
                acc[r][1] += av.x * wv0.y + av.y * wv1.y + av.z * wv2.y + av.w * wv3.y;
                acc[r][2] += av.x * wv0.z + av.y * wv1.z + av.z * wv2.z + av.w * wv3.z;
                acc[r][3] += av.x * wv0.w + av.y * wv1.w + av.z * wv2.w + av.w * wv3.w;
            }
        }
    }
    float4 bv = ld4(bias + tx * 4);
#pragma unroll
    for (int r = 0; r < MR; r++) {
        int n = m0 + r * TY + ty;
        if (n < NN) {
            float4 o;
            o.x = fmaxf(acc[r][0] + bv.x, 0.f);
            o.y = fmaxf(acc[r][1] + bv.y, 0.f);
            o.z = fmaxf(acc[r][2] + bv.z, 0.f);
            o.w = fmaxf(acc[r][3] + bv.w, 0.f);
            *(float4*)(C + (size_t)n * N + tx * 4) = o;
        }
    }
}

// ---------------- tiled GEMM for GAT: h = A@W (fp16 out), fused logits ----------------
template <int K, int N, int MT, int CH>
__global__ __launch_bounds__(128) void gemm_gat(
    const float* __restrict__ A, const float* __restrict__ W,
    const float* __restrict__ asrc, const float* __restrict__ adst) {
    const int KT = 32;
    const int TX = N / 4, TY = 128 / TX, MR = MT / TY;
    __shared__ float At[MT][KT + 4];
    __shared__ float Wt[KT][N];
    int tid = threadIdx.x;
    int tx = tid % TX, ty = tid / TX;
    int m0 = blockIdx.x * MT;
    float acc[MR][4];
#pragma unroll
    for (int r = 0; r < MR; r++)
        for (int j = 0; j < 4; j++) acc[r][j] = 0.f;

    const int T = K / KT;
    for (int t = 0; t < T; t++) {
        __syncthreads();
        const int FR = KT / 4;
        for (int idx = tid; idx < MT * FR; idx += 128) {
            int m = idx / FR, kq = idx % FR;
            int gm = m0 + m; if (gm >= NN) gm = NN - 1;
            *(float4*)&At[m][4 * kq] = ld4(A + (size_t)gm * K + t * KT + 4 * kq);
        }
        for (int idx = tid; idx < KT * N / 4; idx += 128) {
            int row = idx / (N / 4), cq = idx % (N / 4);
            *(float4*)&Wt[row][4 * cq] = ld4(W + (t * KT + row) * N + 4 * cq);
        }
        __syncthreads();
#pragma unroll
        for (int kk = 0; kk < KT; kk += 4) {
            float4 wv0 = *(const float4*)&Wt[kk + 0][tx * 4];
            float4 wv1 = *(const float4*)&Wt[kk + 1][tx * 4];
            float4 wv2 = *(const float4*)&Wt[kk + 2][tx * 4];
            float4 wv3 = *(const float4*)&Wt[kk + 3][tx * 4];
#pragma unroll
            for (int r = 0; r < MR; r++) {
                float4 av = *(const float4*)&At[r * TY + ty][kk];
                acc[r][0] += av.x * wv0.x + av.y * wv1.x + av.z * wv2.x + av.w * wv3.x;
                acc[r][1] += av.x * wv0.y + av.y * wv1.y + av.z * wv2.y + av.w * wv3.y;
                acc[r][2] += av.x * wv0.z + av.y * wv1.z + av.z * wv2.z + av.w * wv3.z;
                acc[r][3] += av.x * wv0.w + av.y * wv1.w + av.z * wv2.w + av.w * wv3.w;
            }
        }
    }
    // epilogue: write h (fp16), per-head logits via shfl reduction
    const int GL = CH / 4;
    float4 as = ld4(asrc + tx * 4);
    float4 ad = ld4(adst + tx * 4);
    int head = (tx * 4) / CH;
#pragma unroll
    for (int r = 0; r < MR; r++) {
        int n = m0 + r * TY + ty;
        bool ok = n < NN;
        float4 hv;
        hv.x = acc[r][0]; hv.y = acc[r][1]; hv.z = acc[r][2]; hv.w = acc[r][3];
        if (ok) {
            __half2 h0 = __floats2half2_rn(hv.x, hv.y);
            __half2 h1 = __floats2half2_rn(hv.z, hv.w);
            uint2 st;
            st.x = *(unsigned*)&h0;
            st.y = *(unsigned*)&h1;
            *(uint2*)(g_h + (size_t)n * N + tx * 4) = st;
        }
        float ps = hv.x * as.x + hv.y * as.y + hv.z * as.z + hv.w * as.w;
        float pd = hv.x * ad.x + hv.y * ad.y + hv.z * ad.z + hv.w * ad.w;
#pragma unroll
        for (int off = 1; off < GL; off <<= 1) {
            ps += __shfl_xor_sync(0xffffffffu, ps, off);
            pd += __shfl_xor_sync(0xffffffffu, pd, off);
        }
        if (ok && (tx % GL) == 0) {
            g_al[n * 8 + head] = ps;
            g_al[n * 8 + 4 + head] = pd;
        }
    }
}

// ---------------- per-edge softmax numerators ----------------
__device__ __forceinline__ float lrexp(float v) {
    v = v > 0.f ? v : 0.2f * v;
    return __expf(v);
}

__global__ void ev_kernel(const int* __restrict__ src, const int* __restrict__ dst) {
    int e = blockIdx.x * blockDim.x + threadIdx.x;
    if (e >= EE) return;
    int s = src[e], d = dst[e], pos = g_pos[e];
    float4 as = *(const float4*)(g_al + (size_t)s * 8);
    float4 ad = *(const float4*)(g_al + (size_t)d * 8 + 4);
    float4 ev;
    ev.x = lrexp(as.x + ad.x);
    ev.y = lrexp(as.y + ad.y);
    ev.z = lrexp(as.z + ad.z);
    ev.w = lrexp(as.w + ad.w);
    *(float4*)(g_ev + (size_t)pos * 4) = ev;
}

// ---------------- GAT gather: warp-per-node, sync-free, fp16 rows ----------------
template <int WPB>
__global__ __launch_bounds__(32 * WPB) void gat_concat_warp(
    const float* __restrict__ bias, float* __restrict__ out) {
    int wid = threadIdx.x >> 5, lane = threadIdx.x & 31;
    int n = blockIdx.x * WPB + wid;
    if (n >= NN) return;
    int h = lane >> 3;
    float4 acc = make_float4(0.f, 0.f, 0.f, 0.f);
    float z = 0.f;
    int k1 = g_row_off[n + 1];
    int k = g_row_off[n];
    for (; k + 4 <= k1; k += 4) {
        int s0 = g_adj[k + 0] & 0xFFFF, s1 = g_adj[k + 1] & 0xFFFF;
        int s2 = g_adj[k + 2] & 0xFFFF, s3 = g_adj[k + 3] & 0xFFFF;
        float e0 = __ldg(g_ev + (size_t)(k + 0) * 4 + h);
        float e1 = __ldg(g_ev + (size_t)(k + 1) * 4 + h);
        float e2 = __ldg(g_ev + (size_t)(k + 2) * 4 + h);
        float e3 = __ldg(g_ev + (size_t)(k + 3) * 4 + h);
        float4 h0 = ldh4(g_h + (size_t)s0 * 128 + 4 * lane);
        float4 h1 = ldh4(g_h + (size_t)s1 * 128 + 4 * lane);
        float4 h2 = ldh4(g_h + (size_t)s2 * 128 + 4 * lane);
        float4 h3 = ldh4(g_h + (size_t)s3 * 128 + 4 * lane);
        z += (e0 + e1) + (e2 + e3);
        acc.x += e0 * h0.x + e1 * h1.x + e2 * h2.x + e3 * h3.x;
        acc.y += e0 * h0.y + e1 * h1.y + e2 * h2.y + e3 * h3.y;
        acc.z += e0 * h0.z + e1 * h1.z + e2 * h2.z + e3 * h3.z;
        acc.w += e0 * h0.w + e1 * h1.w + e2 * h2.w + e3 * h3.w;
    }
    for (; k < k1; k++) {
        int s = g_adj[k] & 0xFFFF;
        float e = __ldg(g_ev + (size_t)k * 4 + h);
        float4 hv = ldh4(g_h + (size_t)s * 128 + 4 * lane);
        z += e;
        acc.x += e * hv.x; acc.y += e * hv.y; acc.z += e * hv.z; acc.w += e * hv.w;
    }
    {   // self loop
        float e = lrexp(g_al[(size_t)n * 8 + h] + g_al[(size_t)n * 8 + 4 + h]);
        float4 hv = ldh4(g_h + (size_t)n * 128 + 4 * lane);
        z += e;
        acc.x += e * hv.x; acc.y += e * hv.y; acc.z += e * hv.z; acc.w += e * hv.w;
    }
    float inv = 1.f / z;
    float4 b = __ldg((const float4*)bias + lane);
    float4 o;
    o.x = acc.x * inv + b.x;
    o.y = acc.y * inv + b.y;
    o.z = acc.z * inv + b.z;
    o.w = acc.w * inv + b.w;
    ((float4*)out)[(size_t)n * 32 + lane] = o;
}

template <int WPB>
__global__ __launch_bounds__(32 * WPB) void gat_mean_warp(
    const float* __restrict__ bias, float* __restrict__ out) {
    int wid = threadIdx.x >> 5, lane = threadIdx.x & 31;
    int n = blockIdx.x * WPB + wid;
    if (n >= NN) return;
    int h = lane >> 3;
    float ax = 0.f, ay = 0.f, z = 0.f;
    int k1 = g_row_off[n + 1];
    int k = g_row_off[n];
    for (; k + 4 <= k1; k += 4) {
        int s0 = g_adj[k + 0] & 0xFFFF, s1 = g_adj[k + 1] & 0xFFFF;
        int s2 = g_adj[k + 2] & 0xFFFF, s3 = g_adj[k + 3] & 0xFFFF;
        float e0 = __ldg(g_ev + (size_t)(k + 0) * 4 + h);
        float e1 = __ldg(g_ev + (size_t)(k + 1) * 4 + h);
        float e2 = __ldg(g_ev + (size_t)(k + 2) * 4 + h);
        float e3 = __ldg(g_ev + (size_t)(k + 3) * 4 + h);
        float2 h0 = ldh2(g_h + (size_t)s0 * 64 + 2 * lane);
        float2 h1 = ldh2(g_h + (size_t)s1 * 64 + 2 * lane);
        float2 h2 = ldh2(g_h + (size_t)s2 * 64 + 2 * lane);
        float2 h3 = ldh2(g_h + (size_t)s3 * 64 + 2 * lane);
        z += (e0 + e1) + (e2 + e3);
        ax += e0 * h0.x + e1 * h1.x + e2 * h2.x + e3 * h3.x;
        ay += e0 * h0.y + e1 * h1.y + e2 * h2.y + e3 * h3.y;
    }
    for (; k < k1; k++) {
        int s = g_adj[k] & 0xFFFF;
        float e = __ldg(g_ev + (size_t)k * 4 + h);
        float2 hv = ldh2(g_h + (size_t)s * 64 + 2 * lane);
        z += e;
        ax += e * hv.x;
        ay += e * hv.y;
    }
    {   // self loop
        float e = lrexp(g_al[(size_t)n * 8 + h] + g_al[(size_t)n * 8 + 4 + h]);
        float2 hv = ldh2(g_h + (size_t)n * 64 + 2 * lane);
        z += e;
        ax += e * hv.x;
        ay += e * hv.y;
    }
    float inv = 1.f / z;
    float vx = ax * inv, vy = ay * inv;
    vx += __shfl_xor_sync(0xffffffffu, vx, 8);
    vy += __shfl_xor_sync(0xffffffffu, vy, 8);
    vx += __shfl_xor_sync(0xffffffffu, vx, 16);
    vy += __shfl_xor_sync(0xffffffffu, vy, 16);
    if (lane < 8) {
        int c = 2 * lane;
        float sx = vx * 0.25f + __ldg(bias + c);
        float sy = vy * 0.25f + __ldg(bias + c + 1);
        sx = fmaxf(sx, 0.f);
        sy = fmaxf(sy, 0.f);
        float2 o;
        o.x = tanhf(sx);
        o.y = tanhf(sy);
        *(float2*)(out + (size_t)n * 16 + c) = o;
    }
}

// ---------------- launch ----------------
extern "C" void kernel_launch(void* const* d_in, const int* in_sizes, int n_in,
                              void* d_out, int out_size) {
    const float* x      = (const float*)d_in[0];
    const int*   ei     = (const int*)d_in[1];
    const int*   et     = (const int*)d_in[2];
    const float* basis1 = (const float*)d_in[3];
    const float* comp1  = (const float*)d_in[4];
    const float* root1  = (const float*)d_in[5];
    const float* brg1   = (const float*)d_in[6];
    const float* wg1    = (const float*)d_in[7];
    const float* asrc1  = (const float*)d_in[8];
    const float* adst1  = (const float*)d_in[9];
    const float* bg1    = (const float*)d_in[10];
    const float* basis2 = (const float*)d_in[11];
    const float* comp2  = (const float*)d_in[12];
    const float* root2  = (const float*)d_in[13];
    const float* brg2   = (const float*)d_in[14];
    const float* wg2    = (const float*)d_in[15];
    const float* asrc2  = (const float*)d_in[16];
    const float* adst2  = (const float*)d_in[17];
    const float* bg2    = (const float*)d_in[18];
    float* out = (float*)d_out;
    const int* src = ei;
    const int* dst = ei + EE;

    int* p_cnt;
    float *p_x1, *p_x2, *p_x3, *p_z;
    cudaGetSymbolAddress((void**)&p_cnt, g_cnt);
    cudaGetSymbolAddress((void**)&p_x1, g_x1);
    cudaGetSymbolAddress((void**)&p_x2, g_x2);
    cudaGetSymbolAddress((void**)&p_x3, g_x3);
    cudaGetSymbolAddress((void**)&p_z, g_z);

    // --- CSR build ---
    zero_int<<<(NN * RR + 255) / 256, 256>>>(p_cnt, NN * RR);
    hist_kernel<<<(EE + 255) / 256, 256>>>(dst, et);
    scanA<<<NB, 256>>>();
    scanB<<<1, 256>>>();
    scanC<<<NB, 256>>>();
    fill_kernel<<<(EE + 255) / 256, 256>>>(src, dst, et);

    const int WPB = 4;
    int nblk = (NN + WPB - 1) / WPB;

    // ---- RGCN 1: 64 -> 64, relu ----
    rgcn_gather_z<64, WPB><<<nblk, 32 * WPB>>>(x, comp1);
    gemm_rgcn<256, 64, 64, 128><<<(NN + 127) / 128, 128>>>(p_z, x, basis1, root1, brg1, p_x1);
    // ---- GAT 1: 64 -> 4x32 concat ----
    gemm_gat<64, 128, 64, 32><<<(NN + 63) / 64, 128>>>(p_x1, wg1, asrc1, adst1);
    ev_kernel<<<(EE + 255) / 256, 256>>>(src, dst);
    gat_concat_warp<WPB><<<nblk, 32 * WPB>>>(bg1, p_x2);
    // ---- RGCN 2: 128 -> 32, relu ----
    rgcn_gather_z<128, WPB><<<nblk, 32 * WPB>>>(p_x2, comp2);
    gemm_rgcn<512, 128, 32, 128><<<(NN + 127) / 128, 128>>>(p_z, p_x2, basis2, root2, brg2, p_x3);
    // ---- GAT 2: 32 -> 4x16, mean heads, relu, tanh ----
    gemm_gat<32, 64, 128, 16><<<(NN + 127) / 128, 128>>>(p_x3, wg2, asrc2, adst2);
    ev_kernel<<<(EE + 255) / 256, 256>>>(src, dst);
    gat_mean_warp<WPB><<<nblk, 32 * WPB>>>(bg2, out);
}

// round 10
// speedup vs baseline: 1.0961x; 1.0961x over previous
#include <cuda_runtime.h>
#include <cuda_fp16.h>
#include <math.h>

#define NN 50000
#define EE 800000
#define RR 8
#define BB 4
#define NB ((NN + 255) / 256)

// ---------------- scratch (device globals; no allocation) ----------------
__device__ float  g_x1[NN * 64];
__device__ float  g_x2[NN * 128];
__device__ float  g_x3[NN * 32];
__device__ __half g_h[NN * 128];        // GAT features, fp16
__device__ float  g_al[NN * 8];
__device__ float  g_z[(size_t)NN * 512];
__device__ int    g_cnt[NN * RR];
__device__ int    g_row_off[NN + 1];
__device__ int    g_cursor[NN];
__device__ int    g_adj[EE];            // src | (etype<<16)
__device__ int    g_pos[EE];
__device__ float  g_ev[(size_t)EE * 4];
__device__ int    g_nodescan[NN];
__device__ int    g_blocksum[NB];
__device__ int    g_blockoff[NB];

__device__ __forceinline__ float4 ld4(const float* p) { return __ldg((const float4*)p); }
__device__ __forceinline__ float2 ld2(const float* p) { return __ldg((const float2*)p); }

template <int VW>
__device__ __forceinline__ void ldv(float (&d)[VW], const float* p) {
    if (VW == 2) {
        float2 v = ld2(p);
        d[0] = v.x; d[1] = v.y;
    } else {
        float4 v = ld4(p);
        d[0] = v.x; d[1] = v.y; d[2] = v.z; d[3] = v.w;
    }
}

// load 4 halves -> float4
__device__ __forceinline__ float4 ldh4(const __half* p) {
    uint2 raw = __ldg((const uint2*)p);
    __half2 a = *(__half2*)&raw.x;
    __half2 b = *(__half2*)&raw.y;
    float2 fa = __half22float2(a), fb = __half22float2(b);
    return make_float4(fa.x, fa.y, fb.x, fb.y);
}
// load 2 halves -> float2
__device__ __forceinline__ float2 ldh2(const __half* p) {
    __half2 h = __ldg((const __half2*)p);
    return __half22float2(h);
}

// ---------------- CSR build ----------------
__global__ void zero_int(int* __restrict__ p, int n) {
    int i = blockIdx.x * blockDim.x + threadIdx.x;
    if (i < n) p[i] = 0;
}

__global__ void hist_kernel(const int* __restrict__ dst, const int* __restrict__ et) {
    int e = blockIdx.x * blockDim.x + threadIdx.x;
    if (e < EE) atomicAdd(&g_cnt[dst[e] * RR + et[e]], 1);
}

__global__ void scanA() {
    __shared__ int sh[256];
    int t = threadIdx.x;
    int n = blockIdx.x * 256 + t;
    int deg = 0;
    if (n < NN) {
#pragma unroll
        for (int r = 0; r < RR; r++) deg += g_cnt[n * RR + r];
    }
    int val = deg;
    sh[t] = val;
    __syncthreads();
    for (int d = 1; d < 256; d <<= 1) {
        int a = (t >= d) ? sh[t - d] : 0;
        __syncthreads();
        val += a;
        sh[t] = val;
        __syncthreads();
    }
    if (n < NN) g_nodescan[n] = val - deg;
    if (t == 255) g_blocksum[blockIdx.x] = val;
}

__global__ void scanB() {
    __shared__ int sh[256];
    int t = threadIdx.x;
    int own = (t < NB) ? g_blocksum[t] : 0;
    int val = own;
    sh[t] = val;
    __syncthreads();
    for (int d = 1; d < 256; d <<= 1) {
        int a = (t >= d) ? sh[t - d] : 0;
        __syncthreads();
        val += a;
        sh[t] = val;
        __syncthreads();
    }
    if (t < NB) g_blockoff[t] = val - own;
    if (t == NB - 1) g_row_off[NN] = val;
}

__global__ void scanC() {
    int n = blockIdx.x * 256 + threadIdx.x;
    if (n < NN) {
        int off = g_blockoff[blockIdx.x] + g_nodescan[n];
        g_row_off[n] = off;
        g_cursor[n] = off;
    }
}

__global__ void fill_kernel(const int* __restrict__ src, const int* __restrict__ dst,
                            const int* __restrict__ et) {
    int e = blockIdx.x * blockDim.x + threadIdx.x;
    if (e < EE) {
        int d = dst[e];
        int pos = atomicAdd(&g_cursor[d], 1);
        g_adj[pos] = src[e] | (et[e] << 16);
        g_pos[e] = pos;
    }
}

// ---------------- RGCN: warp-per-node gather -> z[n, BB*IN] ----------------
template <int IN, int WPB>
__global__ __launch_bounds__(32 * WPB) void rgcn_gather_z(
    const float* __restrict__ x, const float* __restrict__ comp) {
    const int VW = IN / 32;
    __shared__ float wsh[WPB][RR * BB];
    int wid = threadIdx.x >> 5, lane = threadIdx.x & 31;
    int n = blockIdx.x * WPB + wid;
    if (n >= NN) return;

    if (lane < RR) {
        float ic = 1.f / fmaxf((float)g_cnt[n * RR + lane], 1.f);
#pragma unroll
        for (int b = 0; b < BB; b++) wsh[wid][lane * BB + b] = comp[lane * BB + b] * ic;
    }
    __syncwarp();

    float acc[BB][VW];
#pragma unroll
    for (int b = 0; b < BB; b++)
#pragma unroll
        for (int c = 0; c < VW; c++) acc[b][c] = 0.f;

    int k1 = g_row_off[n + 1];
    int k = g_row_off[n];
    for (; k + 4 <= k1; k += 4) {
        int v[4];
        float xr[4][VW];
#pragma unroll
        for (int j = 0; j < 4; j++) {
            v[j] = g_adj[k + j];
            ldv<VW>(xr[j], x + (size_t)(v[j] & 0xFFFF) * IN + VW * lane);
        }
#pragma unroll
        for (int j = 0; j < 4; j++) {
            const float* w = &wsh[wid][(v[j] >> 16) * BB];
#pragma unroll
            for (int b = 0; b < BB; b++)
#pragma unroll
                for (int c = 0; c < VW; c++) acc[b][c] += w[b] * xr[j][c];
        }
    }
    for (; k < k1; k++) {
        int v = g_adj[k];
        float xr[VW];
        ldv<VW>(xr, x + (size_t)(v & 0xFFFF) * IN + VW * lane);
        const float* w = &wsh[wid][(v >> 16) * BB];
#pragma unroll
        for (int b = 0; b < BB; b++)
#pragma unroll
            for (int c = 0; c < VW; c++) acc[b][c] += w[b] * xr[c];
    }
    float* zp = g_z + (size_t)n * (BB * IN);
#pragma unroll
    for (int b = 0; b < BB; b++) {
        if (VW == 2) {
            float2 o; o.x = acc[b][0]; o.y = acc[b][1];
            *(float2*)(zp + b * IN + 2 * lane) = o;
        } else {
            float4 o; o.x = acc[b][0]; o.y = acc[b][1]; o.z = acc[b][VW - 2]; o.w = acc[b][VW - 1];
            *(float4*)(zp + b * IN + 4 * lane) = o;
        }
    }
}

// ---------------- tiled GEMM: C = A1@W1 + A2@W2 + bias, relu ----------------
template <int K1, int K2, int N, int MT>
__global__ __launch_bounds__(128) void gemm_rgcn(
    const float* __restrict__ A1, const float* __restrict__ A2,
    const float* __restrict__ W1, const float* __restrict__ W2,
    const float* __restrict__ bias, float* __restrict__ C) {
    const int KT = 32;
    const int TX = N / 4, TY = 128 / TX, MR = MT / TY;
    __shared__ float At[MT][KT + 4];
    __shared__ float Wt[KT][N];
    int tid = threadIdx.x;
    int tx = tid % TX, ty = tid / TX;
    int m0 = blockIdx.x * MT;
    float acc[MR][4];
#pragma unroll
    for (int r = 0; r < MR; r++)
        for (int j = 0; j < 4; j++) acc[r][j] = 0.f;

    const int T1 = K1 / KT, T2 = K2 / KT;
    for (int t = 0; t < T1 + T2; t++) {
        const float* A; const float* Wsrc;
        int ks, kstride;
        if (t < T1) { A = A1; ks = t * KT; kstride = K1; Wsrc = W1 + t * KT * N; }
        else        { A = A2; ks = (t - T1) * KT; kstride = K2; Wsrc = W2 + (t - T1) * KT * N; }
        __syncthreads();
        const int FR = KT / 4;
        for (int idx = tid; idx < MT * FR; idx += 128) {
            int m = idx / FR, kq = idx % FR;
            int gm = m0 + m; if (gm >= NN) gm = NN - 1;
            *(float4*)&At[m][4 * kq] = ld4(A + (size_t)gm * kstride + ks + 4 * kq);
        }
        for (int idx = tid; idx < KT * N / 4; idx += 128) {
            int row = idx / (N / 4), cq = idx % (N / 4);
            *(float4*)&Wt[row][4 * cq] = ld4(Wsrc + row * N + 4 * cq);
        }
        __syncthreads();
#pragma unroll
        for (int kk = 0; kk < KT; kk++) {
            float4 wv = *(const float4*)&Wt[kk][tx * 4];
#pragma unroll
            for (int r = 0; r < MR; r++) {
                float av = At[r * TY + ty][kk];
                acc[r][0] += av * wv.x;
                acc[r][1] += av * wv.y;
                acc[r][2] += av * wv.z;
                acc[r][3] += av * wv.w;
            }
        }
    }
    float4 bv = ld4(bias + tx * 4);
#pragma unroll
    for (int r = 0; r < MR; r++) {
        int n = m0 + r * TY + ty;
        if (n < NN) {
            float4 o;
            o.x = fmaxf(acc[r][0] + bv.x, 0.f);
            o.y = fmaxf(acc[r][1] + bv.y, 0.f);
            o.z = fmaxf(acc[r][2] + bv.z, 0.f);
            o.w = fmaxf(acc[r][3] + bv.w, 0.f);
            *(float4*)(C + (size_t)n * N + tx * 4) = o;
        }
    }
}

// ---------------- tiled GEMM for GAT: h = A@W (fp16 out), fused logits ----------------
template <int K, int N, int MT, int CH>
__global__ __launch_bounds__(128) void gemm_gat(
    const float* __restrict__ A, const float* __restrict__ W,
    const float* __restrict__ asrc, const float* __restrict__ adst) {
    const int KT = 32;
    const int TX = N / 4, TY = 128 / TX, MR = MT / TY;
    __shared__ float At[MT][KT + 4];
    __shared__ float Wt[KT][N];
    int tid = threadIdx.x;
    int tx = tid % TX, ty = tid / TX;
    int m0 = blockIdx.x * MT;
    float acc[MR][4];
#pragma unroll
    for (int r = 0; r < MR; r++)
        for (int j = 0; j < 4; j++) acc[r][j] = 0.f;

    const int T = K / KT;
    for (int t = 0; t < T; t++) {
        __syncthreads();
        const int FR = KT / 4;
        for (int idx = tid; idx < MT * FR; idx += 128) {
            int m = idx / FR, kq = idx % FR;
            int gm = m0 + m; if (gm >= NN) gm = NN - 1;
            *(float4*)&At[m][4 * kq] = ld4(A + (size_t)gm * K + t * KT + 4 * kq);
        }
        for (int idx = tid; idx < KT * N / 4; idx += 128) {
            int row = idx / (N / 4), cq = idx % (N / 4);
            *(float4*)&Wt[row][4 * cq] = ld4(W + (t * KT + row) * N + 4 * cq);
        }
        __syncthreads();
#pragma unroll
        for (int kk = 0; kk < KT; kk++) {
            float4 wv = *(const float4*)&Wt[kk][tx * 4];
#pragma unroll
            for (int r = 0; r < MR; r++) {
                float av = At[r * TY + ty][kk];
                acc[r][0] += av * wv.x;
                acc[r][1] += av * wv.y;
                acc[r][2] += av * wv.z;
                acc[r][3] += av * wv.w;
            }
        }
    }
    // epilogue: write h (fp16), per-head logits via shfl reduction
    const int GL = CH / 4;
    float4 as = ld4(asrc + tx * 4);
    float4 ad = ld4(adst + tx * 4);
    int head = (tx * 4) / CH;
#pragma unroll
    for (int r = 0; r < MR; r++) {
        int n = m0 + r * TY + ty;
        bool ok = n < NN;
        float4 hv;
        hv.x = acc[r][0]; hv.y = acc[r][1]; hv.z = acc[r][2]; hv.w = acc[r][3];
        if (ok) {
            __half2 h0 = __floats2half2_rn(hv.x, hv.y);
            __half2 h1 = __floats2half2_rn(hv.z, hv.w);
            uint2 st;
            st.x = *(unsigned*)&h0;
            st.y = *(unsigned*)&h1;
            *(uint2*)(g_h + (size_t)n * N + tx * 4) = st;
        }
        float ps = hv.x * as.x + hv.y * as.y + hv.z * as.z + hv.w * as.w;
        float pd = hv.x * ad.x + hv.y * ad.y + hv.z * ad.z + hv.w * ad.w;
#pragma unroll
        for (int off = 1; off < GL; off <<= 1) {
            ps += __shfl_xor_sync(0xffffffffu, ps, off);
            pd += __shfl_xor_sync(0xffffffffu, pd, off);
        }
        if (ok && (tx % GL) == 0) {
            g_al[n * 8 + head] = ps;
            g_al[n * 8 + 4 + head] = pd;
        }
    }
}

// ---------------- per-edge softmax numerators ----------------
__device__ __forceinline__ float lrexp(float v) {
    v = v > 0.f ? v : 0.2f * v;
    return __expf(v);
}

__global__ void ev_kernel(const int* __restrict__ src, const int* __restrict__ dst) {
    int e = blockIdx.x * blockDim.x + threadIdx.x;
    if (e >= EE) return;
    int s = src[e], d = dst[e], pos = g_pos[e];
    float4 as = *(const float4*)(g_al + (size_t)s * 8);
    float4 ad = *(const float4*)(g_al + (size_t)d * 8 + 4);
    float4 ev;
    ev.x = lrexp(as.x + ad.x);
    ev.y = lrexp(as.y + ad.y);
    ev.z = lrexp(as.z + ad.z);
    ev.w = lrexp(as.w + ad.w);
    *(float4*)(g_ev + (size_t)pos * 4) = ev;
}

// ---------------- GAT gather: warp-per-node, sync-free, fp16 rows ----------------
template <int WPB>
__global__ __launch_bounds__(32 * WPB) void gat_concat_warp(
    const float* __restrict__ bias, float* __restrict__ out) {
    int wid = threadIdx.x >> 5, lane = threadIdx.x & 31;
    int n = blockIdx.x * WPB + wid;
    if (n >= NN) return;
    int h = lane >> 3;
    float4 acc = make_float4(0.f, 0.f, 0.f, 0.f);
    float z = 0.f;
    int k1 = g_row_off[n + 1];
    int k = g_row_off[n];
    for (; k + 4 <= k1; k += 4) {
        int s0 = g_adj[k + 0] & 0xFFFF, s1 = g_adj[k + 1] & 0xFFFF;
        int s2 = g_adj[k + 2] & 0xFFFF, s3 = g_adj[k + 3] & 0xFFFF;
        float e0 = __ldg(g_ev + (size_t)(k + 0) * 4 + h);
        float e1 = __ldg(g_ev + (size_t)(k + 1) * 4 + h);
        float e2 = __ldg(g_ev + (size_t)(k + 2) * 4 + h);
        float e3 = __ldg(g_ev + (size_t)(k + 3) * 4 + h);
        float4 h0 = ldh4(g_h + (size_t)s0 * 128 + 4 * lane);
        float4 h1 = ldh4(g_h + (size_t)s1 * 128 + 4 * lane);
        float4 h2 = ldh4(g_h + (size_t)s2 * 128 + 4 * lane);
        float4 h3 = ldh4(g_h + (size_t)s3 * 128 + 4 * lane);
        z += (e0 + e1) + (e2 + e3);
        acc.x += e0 * h0.x + e1 * h1.x + e2 * h2.x + e3 * h3.x;
        acc.y += e0 * h0.y + e1 * h1.y + e2 * h2.y + e3 * h3.y;
        acc.z += e0 * h0.z + e1 * h1.z + e2 * h2.z + e3 * h3.z;
        acc.w += e0 * h0.w + e1 * h1.w + e2 * h2.w + e3 * h3.w;
    }
    for (; k < k1; k++) {
        int s = g_adj[k] & 0xFFFF;
        float e = __ldg(g_ev + (size_t)k * 4 + h);
        float4 hv = ldh4(g_h + (size_t)s * 128 + 4 * lane);
        z += e;
        acc.x += e * hv.x; acc.y += e * hv.y; acc.z += e * hv.z; acc.w += e * hv.w;
    }
    {   // self loop
        float e = lrexp(g_al[(size_t)n * 8 + h] + g_al[(size_t)n * 8 + 4 + h]);
        float4 hv = ldh4(g_h + (size_t)n * 128 + 4 * lane);
        z += e;
        acc.x += e * hv.x; acc.y += e * hv.y; acc.z += e * hv.z; acc.w += e * hv.w;
    }
    float inv = 1.f / z;
    float4 b = __ldg((const float4*)bias + lane);
    float4 o;
    o.x = acc.x * inv + b.x;
    o.y = acc.y * inv + b.y;
    o.z = acc.z * inv + b.z;
    o.w = acc.w * inv + b.w;
    ((float4*)out)[(size_t)n * 32 + lane] = o;
}

template <int WPB>
__global__ __launch_bounds__(32 * WPB) void gat_mean_warp(
    const float* __restrict__ bias, float* __restrict__ out) {
    int wid = threadIdx.x >> 5, lane = threadIdx.x & 31;
    int n = blockIdx.x * WPB + wid;
    if (n >= NN) return;
    int h = lane >> 3;
    float ax = 0.f, ay = 0.f, z = 0.f;
    int k1 = g_row_off[n + 1];
    int k = g_row_off[n];
    for (; k + 4 <= k1; k += 4) {
        int s0 = g_adj[k + 0] & 0xFFFF, s1 = g_adj[k + 1] & 0xFFFF;
        int s2 = g_adj[k + 2] & 0xFFFF, s3 = g_adj[k + 3] & 0xFFFF;
        float e0 = __ldg(g_ev + (size_t)(k + 0) * 4 + h);
        float e1 = __ldg(g_ev + (size_t)(k + 1) * 4 + h);
        float e2 = __ldg(g_ev + (size_t)(k + 2) * 4 + h);
        float e3 = __ldg(g_ev + (size_t)(k + 3) * 4 + h);
        float2 h0 = ldh2(g_h + (size_t)s0 * 64 + 2 * lane);
        float2 h1 = ldh2(g_h + (size_t)s1 * 64 + 2 * lane);
        float2 h2 = ldh2(g_h + (size_t)s2 * 64 + 2 * lane);
        float2 h3 = ldh2(g_h + (size_t)s3 * 64 + 2 * lane);
        z += (e0 + e1) + (e2 + e3);
        ax += e0 * h0.x + e1 * h1.x + e2 * h2.x + e3 * h3.x;
        ay += e0 * h0.y + e1 * h1.y + e2 * h2.y + e3 * h3.y;
    }
    for (; k < k1; k++) {
        int s = g_adj[k] & 0xFFFF;
        float e = __ldg(g_ev + (size_t)k * 4 + h);
        float2 hv = ldh2(g_h + (size_t)s * 64 + 2 * lane);
        z += e;
        ax += e * hv.x;
        ay += e * hv.y;
    }
    {   // self loop
        float e = lrexp(g_al[(size_t)n * 8 + h] + g_al[(size_t)n * 8 + 4 + h]);
        float2 hv = ldh2(g_h + (size_t)n * 64 + 2 * lane);
        z += e;
        ax += e * hv.x;
        ay += e * hv.y;
    }
    float inv = 1.f / z;
    float vx = ax * inv, vy = ay * inv;
    vx += __shfl_xor_sync(0xffffffffu, vx, 8);
    vy += __shfl_xor_sync(0xffffffffu, vy, 8);
    vx += __shfl_xor_sync(0xffffffffu, vx, 16);
    vy += __shfl_xor_sync(0xffffffffu, vy, 16);
    if (lane < 8) {
        int c = 2 * lane;
        float sx = vx * 0.25f + __ldg(bias + c);
        float sy = vy * 0.25f + __ldg(bias + c + 1);
        sx = fmaxf(sx, 0.f);
        sy = fmaxf(sy, 0.f);
        float2 o;
        o.x = tanhf(sx);
        o.y = tanhf(sy);
        *(float2*)(out + (size_t)n * 16 + c) = o;
    }
}

// ---------------- launch ----------------
extern "C" void kernel_launch(void* const* d_in, const int* in_sizes, int n_in,
                              void* d_out, int out_size) {
    const float* x      = (const float*)d_in[0];
    const int*   ei     = (const int*)d_in[1];
    const int*   et     = (const int*)d_in[2];
    const float* basis1 = (const float*)d_in[3];
    const float* comp1  = (const float*)d_in[4];
    const float* root1  = (const float*)d_in[5];
    const float* brg1   = (const float*)d_in[6];
    const float* wg1    = (const float*)d_in[7];
    const float* asrc1  = (const float*)d_in[8];
    const float* adst1  = (const float*)d_in[9];
    const float* bg1    = (const float*)d_in[10];
    const float* basis2 = (const float*)d_in[11];
    const float* comp2  = (const float*)d_in[12];
    const float* root2  = (const float*)d_in[13];
    const float* brg2   = (const float*)d_in[14];
    const float* wg2    = (const float*)d_in[15];
    const float* asrc2  = (const float*)d_in[16];
    const float* adst2  = (const float*)d_in[17];
    const float* bg2    = (const float*)d_in[18];
    float* out = (float*)d_out;
    const int* src = ei;
    const int* dst = ei + EE;

    int* p_cnt;
    float *p_x1, *p_x2, *p_x3, *p_z;
    cudaGetSymbolAddress((void**)&p_cnt, g_cnt);
    cudaGetSymbolAddress((void**)&p_x1, g_x1);
    cudaGetSymbolAddress((void**)&p_x2, g_x2);
    cudaGetSymbolAddress((void**)&p_x3, g_x3);
    cudaGetSymbolAddress((void**)&p_z, g_z);

    // --- CSR build ---
    zero_int<<<(NN * RR + 255) / 256, 256>>>(p_cnt, NN * RR);
    hist_kernel<<<(EE + 255) / 256, 256>>>(dst, et);
    scanA<<<NB, 256>>>();
    scanB<<<1, 256>>>();
    scanC<<<NB, 256>>>();
    fill_kernel<<<(EE + 255) / 256, 256>>>(src, dst, et);

    const int WPB = 4;
    int nblk = (NN + WPB - 1) / WPB;

    // ---- RGCN 1: 64 -> 64, relu ----
    rgcn_gather_z<64, WPB><<<nblk, 32 * WPB>>>(x, comp1);
    gemm_rgcn<256, 64, 64, 128><<<(NN + 127) / 128, 128>>>(p_z, x, basis1, root1, brg1, p_x1);
    // ---- GAT 1: 64 -> 4x32 concat ----
    gemm_gat<64, 128, 64, 32><<<(NN + 63) / 64, 128>>>(p_x1, wg1, asrc1, adst1);
    ev_kernel<<<(EE + 255) / 256, 256>>>(src, dst);
    gat_concat_warp<WPB><<<nblk, 32 * WPB>>>(bg1, p_x2);
    // ---- RGCN 2: 128 -> 32, relu ----
    rgcn_gather_z<128, WPB><<<nblk, 32 * WPB>>>(p_x2, comp2);
    gemm_rgcn<512, 128, 32, 128><<<(NN + 127) / 128, 128>>>(p_z, p_x2, basis2, root2, brg2, p_x3);
    // ---- GAT 2: 32 -> 4x16, mean heads, relu, tanh ----
    gemm_gat<32, 64, 128, 16><<<(NN + 127) / 128, 128>>>(p_x3, wg2, asrc2, adst2);
    ev_kernel<<<(EE + 255) / 256, 256>>>(src, dst);
    gat_mean_warp<WPB><<<nblk, 32 * WPB>>>(bg2, out);
}